// round 1
// baseline (speedup 1.0000x reference)
#include <cuda_runtime.h>
#include <cuda_bf16.h>
#include <cstdint>

typedef unsigned long long u64;

// ---------------- constants ----------------
#define LSEQ     2048
#define DIMV     32
#define SEGS     4
#define SEG_ROWS 512           // rows per segment
#define CHUNK_R  128           // rows per smem chunk
#define NCHUNK   4             // SEG_ROWS / CHUNK_R
#define NBUF     3
#define THREADS  256
#define NPAIRS   496           // 32*31/2
#define OUTW     528           // 32 + 496

// partial C scratch: [B][SEGS][32*32] fp32 = 8 MB for B=512
__device__ float g_part[512 * SEGS * 1024];

// ---------------- f32x2 helpers ----------------
__device__ __forceinline__ u64 fma2(u64 a, u64 b, u64 c) {
    u64 d;
    asm("fma.rn.f32x2 %0, %1, %2, %3;" : "=l"(d) : "l"(a), "l"(b), "l"(c));
    return d;
}
__device__ __forceinline__ u64 pk(float x, float y) {
    u64 r;
    asm("mov.b64 %0, {%1, %2};" : "=l"(r) : "f"(x), "f"(y));
    return r;
}
__device__ __forceinline__ void upk(u64 v, float& x, float& y) {
    asm("mov.b64 {%0, %1}, %2;" : "=f"(x), "=f"(y) : "l"(v));
}

// ---------------- cp.async helpers ----------------
__device__ __forceinline__ void cp_commit() {
    asm volatile("cp.async.commit_group;");
}
template <int N>
__device__ __forceinline__ void cp_wait() {
    asm volatile("cp.async.wait_group %0;" ::"n"(N));
}

__device__ __forceinline__ void copy_chunk(const float* __restrict__ gseg,
                                           float* sb, int c, int tid) {
    unsigned sb_addr = (unsigned)__cvta_generic_to_shared(sb);
    const char* gsrc = (const char*)(gseg + (size_t)c * CHUNK_R * DIMV);
#pragma unroll
    for (int i = 0; i < 4; i++) {
        unsigned off = (unsigned)tid * 16u + (unsigned)i * 4096u;  // 256 thr * 16B * 4 = 16KB
        asm volatile("cp.async.cg.shared.global [%0], [%1], 16;" ::"r"(sb_addr + off),
                     "l"(gsrc + off));
    }
}

// one outer-product step: acc[4x8 tile] += a[4] (x) b[8]
__device__ __forceinline__ void step_core(u64* acc, float4 av, float4 b0, float4 b1) {
    u64 bb0 = pk(b0.x, b0.y), bb1 = pk(b0.z, b0.w);
    u64 bb2 = pk(b1.x, b1.y), bb3 = pk(b1.z, b1.w);
    u64 a;
    a = pk(av.x, av.x);
    acc[0] = fma2(a, bb0, acc[0]);  acc[1] = fma2(a, bb1, acc[1]);
    acc[2] = fma2(a, bb2, acc[2]);  acc[3] = fma2(a, bb3, acc[3]);
    a = pk(av.y, av.y);
    acc[4] = fma2(a, bb0, acc[4]);  acc[5] = fma2(a, bb1, acc[5]);
    acc[6] = fma2(a, bb2, acc[6]);  acc[7] = fma2(a, bb3, acc[7]);
    a = pk(av.z, av.z);
    acc[8]  = fma2(a, bb0, acc[8]);  acc[9]  = fma2(a, bb1, acc[9]);
    acc[10] = fma2(a, bb2, acc[10]); acc[11] = fma2(a, bb3, acc[11]);
    a = pk(av.w, av.w);
    acc[12] = fma2(a, bb0, acc[12]); acc[13] = fma2(a, bb1, acc[13]);
    acc[14] = fma2(a, bb2, acc[14]); acc[15] = fma2(a, bb3, acc[15]);
}

__device__ __forceinline__ void step(u64* acc, const float* ap, const float* bp) {
    float4 av = *(const float4*)ap;
    float4 b0 = *(const float4*)bp;
    float4 b1 = *(const float4*)(bp + 4);
    step_core(acc, av, b0, b1);
}

// ---------------- kernel 1: partial C per (batch, segment) ----------------
__global__ __launch_bounds__(THREADS, 3) void logsig_part_kernel(const float* __restrict__ x) {
    const int b   = blockIdx.x >> 2;
    const int s   = blockIdx.x & 3;
    const int tid = threadIdx.x;
    const int w   = tid >> 5;
    const int lane = tid & 31;
    const int i0 = (lane & 7) * 4;   // 8 i-tiles of 4
    const int j0 = (lane >> 3) * 8;  // 4 j-tiles of 8

    __shared__ float sbuf[NBUF][CHUNK_R][DIMV];  // exactly 48 KB

    const float* gseg = x + ((size_t)b * LSEQ + (size_t)s * SEG_ROWS) * DIMV;

    // prologue: prefetch chunks 0..2
    copy_chunk(gseg, &sbuf[0][0][0], 0, tid); cp_commit();
    copy_chunk(gseg, &sbuf[1][0][0], 1, tid); cp_commit();
    copy_chunk(gseg, &sbuf[2][0][0], 2, tid); cp_commit();

    // cross-segment boundary row (global row s*512 + 512) preloaded into regs (warp 7 only)
    float4 pb0 = make_float4(0.f, 0.f, 0.f, 0.f), pb1 = pb0;
    if (w == 7 && s < SEGS - 1) {
        const float* gb = x + ((size_t)b * LSEQ + (size_t)s * SEG_ROWS + SEG_ROWS) * DIMV;
        pb0 = *(const float4*)(gb + j0);
        pb1 = *(const float4*)(gb + j0 + 4);
    }

    u64 acc[16];
#pragma unroll
    for (int i = 0; i < 16; i++) acc[i] = 0ull;

#pragma unroll 1
    for (int c = 0; c < NCHUNK; c++) {
        if (c < 2) cp_wait<1>(); else cp_wait<0>();
        __syncthreads();

        const float* bufc = &sbuf[c % NBUF][0][0];
        const float* ap = bufc + (size_t)(w * 16) * DIMV + i0;
        const float* bp = bufc + (size_t)(w * 16 + 1) * DIMV + j0;
#pragma unroll
        for (int it = 0; it < 15; ++it) {
            step(acc, ap, bp);
            ap += DIMV; bp += DIMV;
        }
        if (w < 7) {
            step(acc, ap, bp);                       // row within chunk
        } else if (c < NCHUNK - 1) {
            step(acc, ap, &sbuf[(c + 1) % NBUF][0][j0]);  // next chunk row 0
        } else if (s < SEGS - 1) {
            float4 av = *(const float4*)ap;          // cross-segment boundary
            step_core(acc, av, pb0, pb1);
        }
        // (s == SEGS-1, c == NCHUNK-1, w == 7: iteration l = L-1 doesn't exist -> skip)

        __syncthreads();
        if (c == 0) { copy_chunk(gseg, &sbuf[0][0][0], 3, tid); cp_commit(); }
    }

    // reduce 8 per-warp partials through smem (reuse chunk buffers)
    float* pr = &sbuf[0][0][0];
#pragma unroll
    for (int i = 0; i < 4; i++) {
#pragma unroll
        for (int p = 0; p < 4; p++) {
            float lo, hi;
            upk(acc[i * 4 + p], lo, hi);
            pr[w * 1024 + (i0 + i) * 32 + (j0 + 2 * p)]     = lo;
            pr[w * 1024 + (i0 + i) * 32 + (j0 + 2 * p) + 1] = hi;
        }
    }
    __syncthreads();

    const int e0 = tid * 4;
    float4 sum = make_float4(0.f, 0.f, 0.f, 0.f);
#pragma unroll
    for (int ww = 0; ww < 8; ww++) {
        float4 v = *(const float4*)&pr[ww * 1024 + e0];
        sum.x += v.x; sum.y += v.y; sum.z += v.z; sum.w += v.w;
    }
    *(float4*)&g_part[((size_t)b * SEGS + s) * 1024 + e0] = sum;
}

// ---------------- kernel 2: combine + outputs ----------------
__global__ __launch_bounds__(THREADS) void logsig_final_kernel(const float* __restrict__ x,
                                                               float* __restrict__ out) {
    const int b = blockIdx.x;
    const int tid = threadIdx.x;

    __shared__ float Cs[1024];
    __shared__ float x0s[DIMV];
    __shared__ float l1s[DIMV];

    const int e0 = tid * 4;
    float4 sum = make_float4(0.f, 0.f, 0.f, 0.f);
#pragma unroll
    for (int s = 0; s < SEGS; s++) {
        float4 v = *(const float4*)&g_part[((size_t)b * SEGS + s) * 1024 + e0];
        sum.x += v.x; sum.y += v.y; sum.z += v.z; sum.w += v.w;
    }
    *(float4*)&Cs[e0] = sum;

    if (tid < DIMV) {
        float x0 = x[(size_t)b * LSEQ * DIMV + tid];
        float xl = x[(size_t)b * LSEQ * DIMV + (size_t)(LSEQ - 1) * DIMV + tid];
        float l1 = xl - x0;
        x0s[tid] = x0;
        l1s[tid] = l1;
        out[(size_t)b * OUTW + tid] = l1;  // level1
    }
    __syncthreads();

    for (int p = tid; p < NPAIRS; p += blockDim.x) {
        int i = 0, base = 0;
        while (base + (31 - i) <= p) { base += 31 - i; ++i; }
        int j = i + 1 + (p - base);
        float val = 0.5f * ((Cs[i * 32 + j] - Cs[j * 32 + i])
                            - x0s[i] * l1s[j] + x0s[j] * l1s[i]);
        out[(size_t)b * OUTW + DIMV + p] = val;
    }
}

// ---------------- launch ----------------
extern "C" void kernel_launch(void* const* d_in, const int* in_sizes, int n_in,
                              void* d_out, int out_size) {
    const float* x = (const float*)d_in[0];
    float* out = (float*)d_out;
    const int B = in_sizes[0] / (LSEQ * DIMV);  // 512

    logsig_part_kernel<<<B * SEGS, THREADS>>>(x);
    logsig_final_kernel<<<B, THREADS>>>(x, out);
}